// round 11
// baseline (speedup 1.0000x reference)
#include <cuda_runtime.h>
#include <cuda_bf16.h>
#include <math.h>
#include <stdint.h>

// Problem constants (fixed by setup_inputs)
#define BATCH  4
#define LSEQ   2048
#define DMODEL 2048
#define HID    2048
#define NH     32
#define DHEAD  64
#define WIN    64
#define NB     (LSEQ / WIN)      // 32
#define SINKS  16
#define NKEY   (SINKS + 3 * WIN) // 208
#define TPAD   68
#define PPAD   209

// GEMM tiling
#define BM 128
#define BN 256
#define BK 16
#define SMS_A 136   // k-row stride (words) for A tile; 136 % 32 == 8
#define SMS_B 264   // k-row stride (words) for B tile; 264 % 32 == 8
#define AWORDS (BK * SMS_A)               // 2176
#define BWORDS (BK * SMS_B)               // 4224
#define GEMM_SMEM_BYTES ((2 * AWORDS + 2 * BWORDS) * 4)   // 51200

// Scratch (allocation-free: __device__ globals)
__device__ float g_qkv[(size_t)BATCH * LSEQ * 3 * HID];   // [B*L, 3H]
__device__ float g_att[(size_t)BATCH * LSEQ * HID];       // [B*L, H]

__device__ __forceinline__ unsigned f2tf32(float x) {
    unsigned u;
    asm("cvt.rna.tf32.f32 %0, %1;" : "=r"(u) : "f"(x));
    return u;
}

__device__ __forceinline__ void mma_tf32(float c[4], const unsigned a[4],
                                         const unsigned b[2]) {
    asm volatile(
        "mma.sync.aligned.m16n8k8.row.col.f32.tf32.tf32.f32 "
        "{%0,%1,%2,%3}, {%4,%5,%6,%7}, {%8,%9}, {%0,%1,%2,%3};\n"
        : "+f"(c[0]), "+f"(c[1]), "+f"(c[2]), "+f"(c[3])
        : "r"(a[0]), "r"(a[1]), "r"(a[2]), "r"(a[3]), "r"(b[0]), "r"(b[1]));
}

// ---------------------------------------------------------------------------
// C[m,n] = sum_k A[m,k] * W[n,k] + bias[n]   via TF32 mma.sync.
// CTA tile 128x256x16, 256 threads (8 warps), warp tile 64x64.
// Register prefetch + double-buffered smem (1 barrier per k-iter).
// Requires M%128==0, N%256==0, K%16==0.
// ---------------------------------------------------------------------------
__global__ void __launch_bounds__(256) tf32gemm_nt_bias(
    const float* __restrict__ A, const float* __restrict__ W,
    const float* __restrict__ bias, float* __restrict__ C,
    int M, int N, int K)
{
    extern __shared__ unsigned sgm[];
    // layout: As[0], As[1], Bs[0], Bs[1]
    unsigned* Asb[2] = { sgm,              sgm + AWORDS };
    unsigned* Bsb[2] = { sgm + 2 * AWORDS, sgm + 2 * AWORDS + BWORDS };

    const int tid  = threadIdx.x;
    const int warp = tid >> 5;
    const int lane = tid & 31;
    const int lr   = lane >> 2;   // 0..7
    const int lq   = lane & 3;    // 0..3
    const int wm   = warp >> 2;   // 0..1 : m-half (64 rows)
    const int wn   = warp & 3;    // 0..3 : n-quarter (64 cols)

    const int bm = blockIdx.y * BM;
    const int bn = blockIdx.x * BN;

    // per-thread global load coords: A 2 float4, B 4 float4 per tile
    int arow[2], akq[2], brow[4], bkq[4];
#pragma unroll
    for (int p = 0; p < 2; ++p) {
        int f = tid + p * 256;
        arow[p] = f >> 2;          // 0..127 (m)
        akq[p]  = f & 3;
    }
#pragma unroll
    for (int p = 0; p < 4; ++p) {
        int f = tid + p * 256;
        brow[p] = f >> 2;          // 0..255 (n)
        bkq[p]  = f & 3;
    }

    float acc[32][4];
#pragma unroll
    for (int i = 0; i < 32; ++i)
#pragma unroll
        for (int j = 0; j < 4; ++j) acc[i][j] = 0.f;

    float4 pa[2], pw[4];
#pragma unroll
    for (int p = 0; p < 2; ++p)
        pa[p] = *(const float4*)(A + (size_t)(bm + arow[p]) * K + akq[p] * 4);
#pragma unroll
    for (int p = 0; p < 4; ++p)
        pw[p] = *(const float4*)(W + (size_t)(bn + brow[p]) * K + bkq[p] * 4);

    int buf = 0;
    for (int k0 = 0; k0 < K; k0 += BK, buf ^= 1) {
        unsigned* As = Asb[buf];
        unsigned* Bs = Bsb[buf];
        // store current tile (f32 -> tf32 at STS, k-major)
#pragma unroll
        for (int p = 0; p < 2; ++p) {
            int row = arow[p], kq = akq[p];
            As[(kq * 4 + 0) * SMS_A + row] = f2tf32(pa[p].x);
            As[(kq * 4 + 1) * SMS_A + row] = f2tf32(pa[p].y);
            As[(kq * 4 + 2) * SMS_A + row] = f2tf32(pa[p].z);
            As[(kq * 4 + 3) * SMS_A + row] = f2tf32(pa[p].w);
        }
#pragma unroll
        for (int p = 0; p < 4; ++p) {
            int row = brow[p], kq = bkq[p];
            Bs[(kq * 4 + 0) * SMS_B + row] = f2tf32(pw[p].x);
            Bs[(kq * 4 + 1) * SMS_B + row] = f2tf32(pw[p].y);
            Bs[(kq * 4 + 2) * SMS_B + row] = f2tf32(pw[p].z);
            Bs[(kq * 4 + 3) * SMS_B + row] = f2tf32(pw[p].w);
        }
        __syncthreads();   // single barrier per iteration (double-buffered)

        // prefetch next tile (overlaps with MMAs)
        if (k0 + BK < K) {
#pragma unroll
            for (int p = 0; p < 2; ++p)
                pa[p] = *(const float4*)(A + (size_t)(bm + arow[p]) * K + k0 + BK + akq[p] * 4);
#pragma unroll
            for (int p = 0; p < 4; ++p)
                pw[p] = *(const float4*)(W + (size_t)(bn + brow[p]) * K + k0 + BK + bkq[p] * 4);
        }

#pragma unroll
        for (int ks = 0; ks < 2; ++ks) {           // two k=8 steps per tile
            const int kk = ks * 8;
            unsigned a[4][4], b[8][2];
#pragma unroll
            for (int mt = 0; mt < 4; ++mt) {
                int m0 = wm * 64 + mt * 16;
                a[mt][0] = As[(kk + lq)     * SMS_A + m0 + lr];
                a[mt][1] = As[(kk + lq)     * SMS_A + m0 + lr + 8];
                a[mt][2] = As[(kk + lq + 4) * SMS_A + m0 + lr];
                a[mt][3] = As[(kk + lq + 4) * SMS_A + m0 + lr + 8];
            }
#pragma unroll
            for (int nt = 0; nt < 8; ++nt) {
                int n0 = wn * 64 + nt * 8;
                b[nt][0] = Bs[(kk + lq)     * SMS_B + n0 + lr];
                b[nt][1] = Bs[(kk + lq + 4) * SMS_B + n0 + lr];
            }
#pragma unroll
            for (int mt = 0; mt < 4; ++mt)
#pragma unroll
                for (int nt = 0; nt < 8; ++nt)
                    mma_tf32(acc[mt * 8 + nt], a[mt], b[nt]);
        }
        __syncthreads();
    }

    // epilogue: c0 (lr, 2lq), c1 (lr, 2lq+1), c2 (lr+8, 2lq), c3 (lr+8, 2lq+1)
#pragma unroll
    for (int mt = 0; mt < 4; ++mt) {
#pragma unroll
        for (int nt = 0; nt < 8; ++nt) {
            const float* c = acc[mt * 8 + nt];
            int row = bm + wm * 64 + mt * 16 + lr;
            int col = bn + wn * 64 + nt * 8 + 2 * lq;
            float b0 = bias[col], b1 = bias[col + 1];
            float2 v0 = make_float2(c[0] + b0, c[1] + b1);
            float2 v1 = make_float2(c[2] + b0, c[3] + b1);
            *(float2*)(C + (size_t)row * N + col)       = v0;
            *(float2*)(C + (size_t)(row + 8) * N + col) = v1;
        }
    }
}

// ---------------------------------------------------------------------------
// Attention: one block per (window n, head h, batch b). 256 threads. (unchanged)
// ---------------------------------------------------------------------------
__device__ __forceinline__ float rope_inv_freq(int j) {
    return (float)exp2(-(double)j * (13.287712379549449 / 32.0));
}

__global__ void __launch_bounds__(256) attn_kernel(
    const float* __restrict__ qkv,    // [B*L, 3H]
    const float* __restrict__ sinks,  // [NH, SINKS, DHEAD]
    float* __restrict__ Oout)         // [B*L, H]
{
    extern __shared__ float sm[];
    float* Qs = sm;                       // 64*TPAD
    float* Ts = sm + 64 * TPAD;           // 208*TPAD
    float* Ps = Ts + NKEY * TPAD;         // 64*PPAD

    const int n = blockIdx.x;
    const int h = blockIdx.y;
    const int b = blockIdx.z;
    const int tid = threadIdx.x;
    const float scale = 0.125f;

    for (int idx = tid; idx < 64 * 64; idx += 256) {
        int r  = idx >> 6;
        int dd = idx & 63;
        int l  = n * WIN + r;
        const float* qrow = qkv + (size_t)(b * LSEQ + l) * (3 * HID) + h * DHEAD;
        int j = dd & 31;
        float ang = (float)l * rope_inv_freq(j);
        float s, c;
        sincosf(ang, &s, &c);
        float x1 = qrow[j];
        float x2 = qrow[j + 32];
        float val = (dd < 32) ? (x1 * c - x2 * s) : (x1 * s + x2 * c);
        Qs[r * TPAD + dd] = val * scale;
    }
    for (int idx = tid; idx < SINKS * 64; idx += 256) {
        int r  = idx >> 6;
        int dd = idx & 63;
        Ts[r * TPAD + dd] = sinks[((size_t)h * SINKS + r) * DHEAD + dd];
    }
    for (int idx = tid; idx < 3 * WIN * 64; idx += 256) {
        int kk = idx >> 6;
        int dd = idx & 63;
        int bn = n - 1 + kk / WIN;
        float val = 0.f;
        if (bn >= 0 && bn < NB) {
            int lk = bn * WIN + (kk & (WIN - 1));
            const float* krow = qkv + (size_t)(b * LSEQ + lk) * (3 * HID) + HID + h * DHEAD;
            int j = dd & 31;
            float ang = (float)lk * rope_inv_freq(j);
            float s, c;
            sincosf(ang, &s, &c);
            float x1 = krow[j];
            float x2 = krow[j + 32];
            val = (dd < 32) ? (x1 * c - x2 * s) : (x1 * s + x2 * c);
        }
        Ts[(SINKS + kk) * TPAD + dd] = val;
    }
    __syncthreads();

    const int qr   = tid >> 2;
    const int part = tid & 3;
    const int lq   = n * WIN + qr;
    const float* qrowS = Qs + qr * TPAD;

    for (int i = 0; i < NKEY / 4; ++i) {
        int kk = part + 4 * i;
        const float* trow = Ts + kk * TPAD;
        float s = 0.f;
#pragma unroll
        for (int d4 = 0; d4 < 16; ++d4) {
            float4 qv = *(const float4*)(qrowS + d4 * 4);
            float4 tv = *(const float4*)(trow + d4 * 4);
            s += qv.x * tv.x + qv.y * tv.y + qv.z * tv.z + qv.w * tv.w;
        }
        bool valid = true;
        if (kk >= SINKS) {
            int kb = kk - SINKS;
            int bn = n - 1 + kb / WIN;
            int lk = bn * WIN + (kb & (WIN - 1));
            valid = (bn >= 0) && (bn < NB) && (abs(lq - lk) <= WIN);
        }
        Ps[qr * PPAD + kk] = valid ? s : -1e30f;
    }

    float mx = -1e30f;
    for (int i = 0; i < NKEY / 4; ++i)
        mx = fmaxf(mx, Ps[qr * PPAD + part + 4 * i]);
    mx = fmaxf(mx, __shfl_xor_sync(0xffffffffu, mx, 1));
    mx = fmaxf(mx, __shfl_xor_sync(0xffffffffu, mx, 2));
    float sum = 0.f;
    for (int i = 0; i < NKEY / 4; ++i) {
        float e = __expf(Ps[qr * PPAD + part + 4 * i] - mx);
        Ps[qr * PPAD + part + 4 * i] = e;
        sum += e;
    }
    sum += __shfl_xor_sync(0xffffffffu, sum, 1);
    sum += __shfl_xor_sync(0xffffffffu, sum, 2);
    float inv = 1.f / sum;
    for (int i = 0; i < NKEY / 4; ++i)
        Ps[qr * PPAD + part + 4 * i] *= inv;

    __syncthreads();

    for (int idx = tid; idx < 3 * WIN * 64; idx += 256) {
        int kk = idx >> 6;
        int dd = idx & 63;
        int bn = n - 1 + kk / WIN;
        float v = 0.f;
        if (bn >= 0 && bn < NB) {
            int lk = bn * WIN + (kk & (WIN - 1));
            v = qkv[(size_t)(b * LSEQ + lk) * (3 * HID) + 2 * HID + h * DHEAD + dd];
        }
        Ts[(SINKS + kk) * TPAD + dd] = v;
    }
    __syncthreads();

    const int dseg = part * 16;
    float accv[16];
#pragma unroll
    for (int j = 0; j < 16; ++j) accv[j] = 0.f;

    for (int k = 0; k < NKEY; ++k) {
        float p = Ps[qr * PPAD + k];
        const float* vrow = Ts + k * TPAD + dseg;
#pragma unroll
        for (int j4 = 0; j4 < 4; ++j4) {
            float4 vv = *(const float4*)(vrow + j4 * 4);
            accv[j4 * 4 + 0] += p * vv.x;
            accv[j4 * 4 + 1] += p * vv.y;
            accv[j4 * 4 + 2] += p * vv.z;
            accv[j4 * 4 + 3] += p * vv.w;
        }
    }

    float* orow = Oout + (size_t)(b * LSEQ + lq) * HID + h * DHEAD + dseg;
#pragma unroll
    for (int j4 = 0; j4 < 4; ++j4) {
        float4 o;
        o.x = accv[j4 * 4 + 0];
        o.y = accv[j4 * 4 + 1];
        o.z = accv[j4 * 4 + 2];
        o.w = accv[j4 * 4 + 3];
        *(float4*)(orow + j4 * 4) = o;
    }
}

// ---------------------------------------------------------------------------
extern "C" void kernel_launch(void* const* d_in, const int* in_sizes, int n_in,
                              void* d_out, int out_size)
{
    const float* u     = (const float*)d_in[0];
    const float* Wqkv  = (const float*)d_in[1];
    const float* bqkv  = (const float*)d_in[2];
    const float* Wo    = (const float*)d_in[3];
    const float* bo    = (const float*)d_in[4];
    const float* sinks = (const float*)d_in[5];
    float* y = (float*)d_out;

    void* p;
    cudaGetSymbolAddress(&p, g_qkv);
    float* qkv = (float*)p;
    cudaGetSymbolAddress(&p, g_att);
    float* att = (float*)p;

    const int M = BATCH * LSEQ;   // 8192

    cudaFuncSetAttribute(tf32gemm_nt_bias,
                         cudaFuncAttributeMaxDynamicSharedMemorySize, GEMM_SMEM_BYTES);

    // 1) qkv = u @ Wqkv^T + bqkv     [8192, 6144]
    {
        dim3 grid(3 * HID / BN, M / BM);
        tf32gemm_nt_bias<<<grid, 256, GEMM_SMEM_BYTES>>>(u, Wqkv, bqkv, qkv, M, 3 * HID, DMODEL);
    }

    // 2) attention (RoPE fused)
    {
        const int smem = (64 * TPAD + NKEY * TPAD + 64 * PPAD) * (int)sizeof(float);
        cudaFuncSetAttribute(attn_kernel, cudaFuncAttributeMaxDynamicSharedMemorySize, smem);
        dim3 grid(NB, NH, BATCH);
        attn_kernel<<<grid, 256, smem>>>(qkv, sinks, att);
    }

    // 3) y = att @ Wo^T + bo         [8192, 2048]
    {
        dim3 grid(DMODEL / BN, M / BM);
        tf32gemm_nt_bias<<<grid, 256, GEMM_SMEM_BYTES>>>(att, Wo, bo, y, M, DMODEL, HID);
    }
}

// round 14
// speedup vs baseline: 1.3197x; 1.3197x over previous
#include <cuda_runtime.h>
#include <cuda_bf16.h>
#include <math.h>
#include <stdint.h>

// Problem constants (fixed by setup_inputs)
#define BATCH  4
#define LSEQ   2048
#define DMODEL 2048
#define HID    2048
#define NH     32
#define DHEAD  64
#define WIN    64
#define NB     (LSEQ / WIN)      // 32
#define SINKS  16
#define NKEY   (SINKS + 3 * WIN) // 208
#define TPAD   68
#define PPAD   209
#define SMS    136               // smem row stride (words) for GEMM tiles

// Scratch (allocation-free: __device__ globals)
__device__ float g_qkv[(size_t)BATCH * LSEQ * 3 * HID];   // [B*L, 3H]
__device__ float g_att[(size_t)BATCH * LSEQ * HID];       // [B*L, H]

__device__ __forceinline__ unsigned f2tf32(float x) {
    unsigned u;
    asm("cvt.rna.tf32.f32 %0, %1;" : "=r"(u) : "f"(x));
    return u;
}

__device__ __forceinline__ void mma_tf32(float c[4], const unsigned a[4],
                                         const unsigned b[2]) {
    asm volatile(
        "mma.sync.aligned.m16n8k8.row.col.f32.tf32.tf32.f32 "
        "{%0,%1,%2,%3}, {%4,%5,%6,%7}, {%8,%9}, {%0,%1,%2,%3};\n"
        : "+f"(c[0]), "+f"(c[1]), "+f"(c[2]), "+f"(c[3])
        : "r"(a[0]), "r"(a[1]), "r"(a[2]), "r"(a[3]), "r"(b[0]), "r"(b[1]));
}

// ---------------------------------------------------------------------------
// R7 GEMM (known-good, 4663us config): CTA 128x128x16, 256 threads, warp 64x32.
// Register prefetch + double-buffered smem, SMS=136 conflict-free fragments.
// ---------------------------------------------------------------------------
__global__ void __launch_bounds__(256) tf32gemm_nt_bias(
    const float* __restrict__ A, const float* __restrict__ W,
    const float* __restrict__ bias, float* __restrict__ C,
    int M, int N, int K)
{
    __shared__ unsigned As[2][16 * SMS];
    __shared__ unsigned Bs[2][16 * SMS];

    const int tid  = threadIdx.x;
    const int warp = tid >> 5;
    const int lane = tid & 31;
    const int lr   = lane >> 2;   // 0..7
    const int lq   = lane & 3;    // 0..3
    const int wm   = warp >> 2;   // 0..1 : m-half (64 rows)
    const int wn   = warp & 3;    // 0..3 : n-quarter (32 cols)

    const int bm = blockIdx.y * 128;
    const int bn = blockIdx.x * 128;

    int lrow[2], lkq[2];
#pragma unroll
    for (int p = 0; p < 2; ++p) {
        int f = tid + p * 256;
        lrow[p] = f >> 2;          // 0..127
        lkq[p]  = f & 3;           // 0..3
    }

    float acc[16][4];
#pragma unroll
    for (int i = 0; i < 16; ++i)
#pragma unroll
        for (int j = 0; j < 4; ++j) acc[i][j] = 0.f;

    float4 pa[2], pw[2];
#pragma unroll
    for (int p = 0; p < 2; ++p) {
        pa[p] = *(const float4*)(A + (size_t)(bm + lrow[p]) * K + lkq[p] * 4);
        pw[p] = *(const float4*)(W + (size_t)(bn + lrow[p]) * K + lkq[p] * 4);
    }

    int buf = 0;
    for (int k0 = 0; k0 < K; k0 += 16, buf ^= 1) {
#pragma unroll
        for (int p = 0; p < 2; ++p) {
            int row = lrow[p], kq = lkq[p];
            As[buf][(kq * 4 + 0) * SMS + row] = f2tf32(pa[p].x);
            As[buf][(kq * 4 + 1) * SMS + row] = f2tf32(pa[p].y);
            As[buf][(kq * 4 + 2) * SMS + row] = f2tf32(pa[p].z);
            As[buf][(kq * 4 + 3) * SMS + row] = f2tf32(pa[p].w);
            Bs[buf][(kq * 4 + 0) * SMS + row] = f2tf32(pw[p].x);
            Bs[buf][(kq * 4 + 1) * SMS + row] = f2tf32(pw[p].y);
            Bs[buf][(kq * 4 + 2) * SMS + row] = f2tf32(pw[p].z);
            Bs[buf][(kq * 4 + 3) * SMS + row] = f2tf32(pw[p].w);
        }
        __syncthreads();

        if (k0 + 16 < K) {
#pragma unroll
            for (int p = 0; p < 2; ++p) {
                pa[p] = *(const float4*)(A + (size_t)(bm + lrow[p]) * K + k0 + 16 + lkq[p] * 4);
                pw[p] = *(const float4*)(W + (size_t)(bn + lrow[p]) * K + k0 + 16 + lkq[p] * 4);
            }
        }

#pragma unroll
        for (int ks = 0; ks < 2; ++ks) {
            const int kk = ks * 8;
            unsigned a[4][4], b[4][2];
#pragma unroll
            for (int mt = 0; mt < 4; ++mt) {
                int m0 = wm * 64 + mt * 16;
                a[mt][0] = As[buf][(kk + lq)     * SMS + m0 + lr];
                a[mt][1] = As[buf][(kk + lq)     * SMS + m0 + lr + 8];
                a[mt][2] = As[buf][(kk + lq + 4) * SMS + m0 + lr];
                a[mt][3] = As[buf][(kk + lq + 4) * SMS + m0 + lr + 8];
            }
#pragma unroll
            for (int nt = 0; nt < 4; ++nt) {
                int n0 = wn * 32 + nt * 8;
                b[nt][0] = Bs[buf][(kk + lq)     * SMS + n0 + lr];
                b[nt][1] = Bs[buf][(kk + lq + 4) * SMS + n0 + lr];
            }
#pragma unroll
            for (int mt = 0; mt < 4; ++mt)
#pragma unroll
                for (int nt = 0; nt < 4; ++nt)
                    mma_tf32(acc[mt * 4 + nt], a[mt], b[nt]);
        }
        __syncthreads();
    }

#pragma unroll
    for (int mt = 0; mt < 4; ++mt) {
#pragma unroll
        for (int nt = 0; nt < 4; ++nt) {
            const float* c = acc[mt * 4 + nt];
            int row = bm + wm * 64 + mt * 16 + lr;
            int col = bn + wn * 32 + nt * 8 + 2 * lq;
            float b0 = bias[col], b1 = bias[col + 1];
            float2 v0 = make_float2(c[0] + b0, c[1] + b1);
            float2 v1 = make_float2(c[2] + b0, c[3] + b1);
            *(float2*)(C + (size_t)row * N + col)       = v0;
            *(float2*)(C + (size_t)(row + 8) * N + col) = v1;
        }
    }
}

// ---------------------------------------------------------------------------
// Attention: one block per (window n, head h, batch b). 512 threads (was 256):
// 8 lanes per q-row (part = tid&7), doubling warps/SMSP for latency hiding.
// ---------------------------------------------------------------------------
__device__ __forceinline__ float rope_inv_freq(int j) {
    return (float)exp2(-(double)j * (13.287712379549449 / 32.0));
}

__global__ void __launch_bounds__(512) attn_kernel(
    const float* __restrict__ qkv,    // [B*L, 3H]
    const float* __restrict__ sinks,  // [NH, SINKS, DHEAD]
    float* __restrict__ Oout)         // [B*L, H]
{
    extern __shared__ float sm[];
    float* Qs = sm;                       // 64*TPAD
    float* Ts = sm + 64 * TPAD;           // 208*TPAD
    float* Ps = Ts + NKEY * TPAD;         // 64*PPAD

    const int n = blockIdx.x;
    const int h = blockIdx.y;
    const int b = blockIdx.z;
    const int tid = threadIdx.x;
    const float scale = 0.125f;

    // ---- load Q (RoPE + scale) ----
    for (int idx = tid; idx < 64 * 64; idx += 512) {
        int r  = idx >> 6;
        int dd = idx & 63;
        int l  = n * WIN + r;
        const float* qrow = qkv + (size_t)(b * LSEQ + l) * (3 * HID) + h * DHEAD;
        int j = dd & 31;
        float ang = (float)l * rope_inv_freq(j);
        float s, c;
        sincosf(ang, &s, &c);
        float x1 = qrow[j];
        float x2 = qrow[j + 32];
        float val = (dd < 32) ? (x1 * c - x2 * s) : (x1 * s + x2 * c);
        Qs[r * TPAD + dd] = val * scale;
    }
    // ---- sinks into Ts rows 0..15 ----
    for (int idx = tid; idx < SINKS * 64; idx += 512) {
        int r  = idx >> 6;
        int dd = idx & 63;
        Ts[r * TPAD + dd] = sinks[((size_t)h * SINKS + r) * DHEAD + dd];
    }
    // ---- K band (RoPE) into Ts rows 16..207 ----
    for (int idx = tid; idx < 3 * WIN * 64; idx += 512) {
        int kk = idx >> 6;
        int dd = idx & 63;
        int bn = n - 1 + kk / WIN;
        float val = 0.f;
        if (bn >= 0 && bn < NB) {
            int lk = bn * WIN + (kk & (WIN - 1));
            const float* krow = qkv + (size_t)(b * LSEQ + lk) * (3 * HID) + HID + h * DHEAD;
            int j = dd & 31;
            float ang = (float)lk * rope_inv_freq(j);
            float s, c;
            sincosf(ang, &s, &c);
            float x1 = krow[j];
            float x2 = krow[j + 32];
            val = (dd < 32) ? (x1 * c - x2 * s) : (x1 * s + x2 * c);
        }
        Ts[(SINKS + kk) * TPAD + dd] = val;
    }
    __syncthreads();

    // ---- scores: thread (qr, part) computes keys kk = part + 8*i ----
    const int qr   = tid >> 3;     // 0..63
    const int part = tid & 7;      // 0..7
    const int lq   = n * WIN + qr;
    const float* qrowS = Qs + qr * TPAD;

    for (int i = 0; i < NKEY / 8; ++i) {   // 26 iterations
        int kk = part + 8 * i;
        const float* trow = Ts + kk * TPAD;
        float s = 0.f;
#pragma unroll
        for (int d4 = 0; d4 < 16; ++d4) {
            float4 qv = *(const float4*)(qrowS + d4 * 4);
            float4 tv = *(const float4*)(trow + d4 * 4);
            s += qv.x * tv.x + qv.y * tv.y + qv.z * tv.z + qv.w * tv.w;
        }
        bool valid = true;
        if (kk >= SINKS) {
            int kb = kk - SINKS;
            int bn = n - 1 + kb / WIN;
            int lk = bn * WIN + (kb & (WIN - 1));
            valid = (bn >= 0) && (bn < NB) && (abs(lq - lk) <= WIN);
        }
        Ps[qr * PPAD + kk] = valid ? s : -1e30f;
    }

    // ---- softmax per row: 8 lanes per row, 8-aligned within warp ----
    float mx = -1e30f;
    for (int i = 0; i < NKEY / 8; ++i)
        mx = fmaxf(mx, Ps[qr * PPAD + part + 8 * i]);
    mx = fmaxf(mx, __shfl_xor_sync(0xffffffffu, mx, 1));
    mx = fmaxf(mx, __shfl_xor_sync(0xffffffffu, mx, 2));
    mx = fmaxf(mx, __shfl_xor_sync(0xffffffffu, mx, 4));
    float sum = 0.f;
    for (int i = 0; i < NKEY / 8; ++i) {
        float e = __expf(Ps[qr * PPAD + part + 8 * i] - mx);
        Ps[qr * PPAD + part + 8 * i] = e;
        sum += e;
    }
    sum += __shfl_xor_sync(0xffffffffu, sum, 1);
    sum += __shfl_xor_sync(0xffffffffu, sum, 2);
    sum += __shfl_xor_sync(0xffffffffu, sum, 4);
    float inv = 1.f / sum;
    for (int i = 0; i < NKEY / 8; ++i)
        Ps[qr * PPAD + part + 8 * i] *= inv;

    __syncthreads();  // all scores done; safe to overwrite Ts with V

    // ---- V band into Ts rows 16..207 ----
    for (int idx = tid; idx < 3 * WIN * 64; idx += 512) {
        int kk = idx >> 6;
        int dd = idx & 63;
        int bn = n - 1 + kk / WIN;
        float v = 0.f;
        if (bn >= 0 && bn < NB) {
            int lk = bn * WIN + (kk & (WIN - 1));
            v = qkv[(size_t)(b * LSEQ + lk) * (3 * HID) + 2 * HID + h * DHEAD + dd];
        }
        Ts[(SINKS + kk) * TPAD + dd] = v;
    }
    __syncthreads();

    // ---- O = P @ [sinks; Vband] : thread (qr, part) owns dims part*8..+7 ----
    const int dseg = part * 8;
    float accv[8];
#pragma unroll
    for (int j = 0; j < 8; ++j) accv[j] = 0.f;

    for (int k = 0; k < NKEY; ++k) {
        float p = Ps[qr * PPAD + k];
        const float* vrow = Ts + k * TPAD + dseg;
#pragma unroll
        for (int j4 = 0; j4 < 2; ++j4) {
            float4 vv = *(const float4*)(vrow + j4 * 4);
            accv[j4 * 4 + 0] += p * vv.x;
            accv[j4 * 4 + 1] += p * vv.y;
            accv[j4 * 4 + 2] += p * vv.z;
            accv[j4 * 4 + 3] += p * vv.w;
        }
    }

    float* orow = Oout + (size_t)(b * LSEQ + lq) * HID + h * DHEAD + dseg;
#pragma unroll
    for (int j4 = 0; j4 < 2; ++j4) {
        float4 o;
        o.x = accv[j4 * 4 + 0];
        o.y = accv[j4 * 4 + 1];
        o.z = accv[j4 * 4 + 2];
        o.w = accv[j4 * 4 + 3];
        *(float4*)(orow + j4 * 4) = o;
    }
}

// ---------------------------------------------------------------------------
extern "C" void kernel_launch(void* const* d_in, const int* in_sizes, int n_in,
                              void* d_out, int out_size)
{
    const float* u     = (const float*)d_in[0];
    const float* Wqkv  = (const float*)d_in[1];
    const float* bqkv  = (const float*)d_in[2];
    const float* Wo    = (const float*)d_in[3];
    const float* bo    = (const float*)d_in[4];
    const float* sinks = (const float*)d_in[5];
    float* y = (float*)d_out;

    void* p;
    cudaGetSymbolAddress(&p, g_qkv);
    float* qkv = (float*)p;
    cudaGetSymbolAddress(&p, g_att);
    float* att = (float*)p;

    const int M = BATCH * LSEQ;   // 8192

    // 1) qkv = u @ Wqkv^T + bqkv     [8192, 6144]
    {
        dim3 grid(3 * HID / 128, M / 128);
        tf32gemm_nt_bias<<<grid, 256>>>(u, Wqkv, bqkv, qkv, M, 3 * HID, DMODEL);
    }

    // 2) attention (RoPE fused), 512 threads
    {
        const int smem = (64 * TPAD + NKEY * TPAD + 64 * PPAD) * (int)sizeof(float);
        cudaFuncSetAttribute(attn_kernel, cudaFuncAttributeMaxDynamicSharedMemorySize, smem);
        dim3 grid(NB, NH, BATCH);
        attn_kernel<<<grid, 512, smem>>>(qkv, sinks, att);
    }

    // 3) y = att @ Wo^T + bo         [8192, 2048]
    {
        dim3 grid(DMODEL / 128, M / 128);
        tf32gemm_nt_bias<<<grid, 256>>>(att, Wo, bo, y, M, DMODEL, HID);
    }
}